// round 2
// baseline (speedup 1.0000x reference)
#include <cuda_runtime.h>
#include <math.h>
#include <stdint.h>

#define G 64      // B*T graphs
#define NN 1024   // nodes per graph
#define FF 64     // features
#define JT 128    // j tile width staged in smem
#define WARPS 16  // warps per block in attn kernel

// Scratch (device globals: allocation-free rule)
__device__ float g_Wh[G * NN * FF];   // 16 MB
__device__ float g_s1[G * NN];
__device__ float g_s2[G * NN];

// ---------------------------------------------------------------------------
// Kernel A: Wh = h @ W, s1 = Wh@a1, s2 = Wh@a2.  One warp per node.
// ---------------------------------------------------------------------------
__global__ __launch_bounds__(256) void wh_kernel(const float* __restrict__ h,
                                                 const float* __restrict__ W,
                                                 const float* __restrict__ a) {
    __shared__ float2 Ws[64 * 32];   // 16 KB, same linear layout as W
    int tid = threadIdx.x;
    {
        const float4* W4 = (const float4*)W;
        float4* Ws4 = (float4*)Ws;
        #pragma unroll
        for (int i = 0; i < 4; i++) Ws4[tid + i * 256] = W4[tid + i * 256];
    }
    __syncthreads();

    int lane = tid & 31;
    int warp = tid >> 5;
    int node = blockIdx.x * 8 + warp;            // 0 .. G*NN-1

    float2 hv = ((const float2*)(h + (size_t)node * FF))[lane];

    float accx = 0.f, accy = 0.f;
    #pragma unroll
    for (int k = 0; k < 64; k++) {
        float hk = __shfl_sync(0xffffffffu, (k & 1) ? hv.y : hv.x, k >> 1);
        float2 w2 = Ws[k * 32 + lane];
        accx = fmaf(hk, w2.x, accx);
        accy = fmaf(hk, w2.y, accy);
    }
    ((float2*)(g_Wh + (size_t)node * FF))[lane] = make_float2(accx, accy);

    // scores
    float2 a1 = __ldg(((const float2*)a) + lane);        // a[2l], a[2l+1]
    float2 a2 = __ldg(((const float2*)a) + 32 + lane);   // a[64+2l], ...
    float s1 = accx * a1.x + accy * a1.y;
    float s2 = accx * a2.x + accy * a2.y;
    #pragma unroll
    for (int off = 16; off; off >>= 1) {
        s1 += __shfl_xor_sync(0xffffffffu, s1, off);
        s2 += __shfl_xor_sync(0xffffffffu, s2, off);
    }
    if (lane == 0) { g_s1[node] = s1; g_s2[node] = s2; }
}

// ---------------------------------------------------------------------------
// Kernel C: masked-softmax attention + att@Wh + ELU.
// Block = 512 threads = 16 warps; each warp owns 4 rows i; 64 rows per block.
// Single pass over j (no max subtraction needed: |s1+s2| small, exp safe).
// ---------------------------------------------------------------------------
extern __shared__ float smem_c[];

__global__ __launch_bounds__(512) void attn_kernel(const int* __restrict__ adj,
                                                   float* __restrict__ out) {
    float*  Whs = smem_c;                       // JT*64 floats      (32 KB)
    float*  s2s = smem_c + JT * 64;             // JT floats         (512 B)
    float2* ps  = (float2*)(smem_c + JT * 64 + JT);  // [warp][2][JT] (32 KB)

    int tid  = threadIdx.x;
    int lane = tid & 31;
    int w    = tid >> 5;
    int g    = blockIdx.x >> 4;
    int i0   = (blockIdx.x & 15) * 64 + w * 4;

    float s1r[4];
    #pragma unroll
    for (int r = 0; r < 4; r++) s1r[r] = g_s1[g * NN + i0 + r];

    // acc[0]={r0f0,r1f0} acc[1]={r0f1,r1f1} acc[2]={r2f0,r3f0} acc[3]={r2f1,r3f1}
    unsigned long long acc[4] = {0ull, 0ull, 0ull, 0ull};
    float Zl[4] = {0.f, 0.f, 0.f, 0.f};

    const int*   adjg = adj + ((size_t)g * NN + i0) * NN;
    const float* Whg  = g_Wh + (size_t)g * NN * FF;
    float2* psA = &ps[(w * 2 + 0) * JT];
    float2* psB = &ps[(w * 2 + 1) * JT];

    for (int jt = 0; jt < NN / JT; jt++) {
        int j0 = jt * JT;
        __syncthreads();   // previous tile's Whs reads complete
        {
            const float4* src = (const float4*)(Whg + j0 * FF);
            float4* dst = (float4*)Whs;
            #pragma unroll
            for (int q = 0; q < 4; q++) dst[tid + q * 512] = src[tid + q * 512];
            if (tid < JT) s2s[tid] = g_s2[g * NN + j0 + tid];
        }
        __syncthreads();

        // phase 1: p values for 4 rows x 128 j
        #pragma unroll
        for (int c = 0; c < 4; c++) {
            int jj = c * 32 + lane;
            float s2v = s2s[jj];
            float pv[4];
            #pragma unroll
            for (int r = 0; r < 4; r++) {
                int av = adjg[(size_t)r * NN + j0 + jj];
                float x = s1r[r] + s2v;
                float e = fmaxf(x, 0.2f * x);         // leaky_relu
                float p = av ? __expf(e) : 0.0f;      // masked -> weight 0
                Zl[r] += p;
                pv[r] = p;
            }
            psA[jj] = make_float2(pv[0], pv[1]);
            psB[jj] = make_float2(pv[2], pv[3]);
        }
        __syncwarp();

        // phase 2: rank-JT update with packed f32x2 FMA (rows packed)
        #pragma unroll 8
        for (int jj = 0; jj < JT; jj++) {
            unsigned long long p01 = *(const unsigned long long*)&psA[jj]; // bcast
            unsigned long long p23 = *(const unsigned long long*)&psB[jj]; // bcast
            float w0 = Whs[jj * 64 + 2 * lane];
            float w1 = Whs[jj * 64 + 2 * lane + 1];
            unsigned long long wd0, wd1;
            asm("mov.b64 %0, {%1, %1};" : "=l"(wd0) : "r"(__float_as_uint(w0)));
            asm("mov.b64 %0, {%1, %1};" : "=l"(wd1) : "r"(__float_as_uint(w1)));
            asm("fma.rn.f32x2 %0, %1, %2, %0;" : "+l"(acc[0]) : "l"(p01), "l"(wd0));
            asm("fma.rn.f32x2 %0, %1, %2, %0;" : "+l"(acc[1]) : "l"(p01), "l"(wd1));
            asm("fma.rn.f32x2 %0, %1, %2, %0;" : "+l"(acc[2]) : "l"(p23), "l"(wd0));
            asm("fma.rn.f32x2 %0, %1, %2, %0;" : "+l"(acc[3]) : "l"(p23), "l"(wd1));
        }
    }

    // reduce Z across lanes (each lane held a disjoint subset of j)
    #pragma unroll
    for (int r = 0; r < 4; r++) {
        #pragma unroll
        for (int off = 16; off; off >>= 1)
            Zl[r] += __shfl_xor_sync(0xffffffffu, Zl[r], off);
    }

    // unpack, normalize, ELU, write
    float af[4][2];
    {
        uint2 u;
        u = *(uint2*)&acc[0]; af[0][0] = __uint_as_float(u.x); af[1][0] = __uint_as_float(u.y);
        u = *(uint2*)&acc[1]; af[0][1] = __uint_as_float(u.x); af[1][1] = __uint_as_float(u.y);
        u = *(uint2*)&acc[2]; af[2][0] = __uint_as_float(u.x); af[3][0] = __uint_as_float(u.y);
        u = *(uint2*)&acc[3]; af[2][1] = __uint_as_float(u.x); af[3][1] = __uint_as_float(u.y);
    }
    #pragma unroll
    for (int r = 0; r < 4; r++) {
        float inv = 1.0f / Zl[r];
        float o0 = af[r][0] * inv;
        float o1 = af[r][1] * inv;
        o0 = o0 > 0.f ? o0 : expm1f(o0);   // ELU (alpha=1)
        o1 = o1 > 0.f ? o1 : expm1f(o1);
        ((float2*)(out + ((size_t)g * NN + i0 + r) * FF))[lane] = make_float2(o0, o1);
    }
}

// ---------------------------------------------------------------------------
extern "C" void kernel_launch(void* const* d_in, const int* in_sizes, int n_in,
                              void* d_out, int out_size) {
    const float* h   = (const float*)d_in[0];
    const int*   adj = (const int*)d_in[1];
    const float* W   = (const float*)d_in[2];
    const float* a   = (const float*)d_in[3];
    float* out = (float*)d_out;

    const int smem_bytes = (JT * 64 + JT) * 4 + WARPS * 2 * JT * 8; // 66048
    cudaFuncSetAttribute(attn_kernel, cudaFuncAttributeMaxDynamicSharedMemorySize,
                         smem_bytes);

    wh_kernel<<<G * NN / 8, 256>>>(h, W, a);
    attn_kernel<<<G * (NN / 64), 512, smem_bytes>>>(adj, out);
}

// round 4
// speedup vs baseline: 1.4550x; 1.4550x over previous
#include <cuda_runtime.h>
#include <math.h>
#include <stdint.h>

#define G 64      // B*T graphs
#define NN 1024   // nodes per graph
#define FF 64     // features

// Scratch (device globals: allocation-free rule)
__device__ float g_Wh[G * NN * FF];   // 16 MB
__device__ float g_s1[G * NN];
__device__ float g_s2[G * NN];

__device__ __forceinline__ float f2tf32(float x) {
    float r;
    asm("cvt.rna.tf32.f32 %0, %1;" : "=f"(r) : "f"(x));
    return r;
}

// ---------------------------------------------------------------------------
// Kernel A: Wh = h @ W, s1 = Wh@a1, s2 = Wh@a2.  One warp per node.
// (round-1 version, known correct, full fp32)
// ---------------------------------------------------------------------------
__global__ __launch_bounds__(256) void wh_kernel(const float* __restrict__ h,
                                                 const float* __restrict__ W,
                                                 const float* __restrict__ a) {
    __shared__ float2 Ws[64 * 32];
    int tid = threadIdx.x;
    {
        const float4* W4 = (const float4*)W;
        float4* Ws4 = (float4*)Ws;
        #pragma unroll
        for (int i = 0; i < 4; i++) Ws4[tid + i * 256] = W4[tid + i * 256];
    }
    __syncthreads();

    int lane = tid & 31;
    int warp = tid >> 5;
    int node = blockIdx.x * 8 + warp;

    float2 hv = ((const float2*)(h + (size_t)node * FF))[lane];

    float accx = 0.f, accy = 0.f;
    #pragma unroll
    for (int k = 0; k < 64; k++) {
        float hk = __shfl_sync(0xffffffffu, (k & 1) ? hv.y : hv.x, k >> 1);
        float2 w2 = Ws[k * 32 + lane];
        accx = fmaf(hk, w2.x, accx);
        accy = fmaf(hk, w2.y, accy);
    }
    ((float2*)(g_Wh + (size_t)node * FF))[lane] = make_float2(accx, accy);

    float2 a1 = __ldg(((const float2*)a) + lane);
    float2 a2 = __ldg(((const float2*)a) + 32 + lane);
    float s1 = accx * a1.x + accy * a1.y;
    float s2 = accx * a2.x + accy * a2.y;
    #pragma unroll
    for (int off = 16; off; off >>= 1) {
        s1 += __shfl_xor_sync(0xffffffffu, s1, off);
        s2 += __shfl_xor_sync(0xffffffffu, s2, off);
    }
    if (lane == 0) { g_s1[node] = s1; g_s2[node] = s2; }
}

// ---------------------------------------------------------------------------
// Kernel C: out[128,64] = softmax_mask(P) @ Wh via mma.sync m16n8k8 tf32.
// 8 warps; warp w owns rows [i0+16w, i0+16w+16). A-fragments (P values)
// generated in registers from adj + s1 + s2; B (WhT chunk) staged in smem.
// ---------------------------------------------------------------------------
#define BPITCH 72   // smem row pitch (floats) for Whs -> conflict-free LDS

__global__ __launch_bounds__(256, 3) void attn_mma(const int* __restrict__ adj,
                                                   float* __restrict__ out) {
    __shared__ float s2s[NN];            // 4 KB
    __shared__ float Whs[32 * BPITCH];   // 9.2 KB  [k][n], tf32-rounded

    const int tid  = threadIdx.x;
    const int lane = tid & 31;
    const int w    = tid >> 5;
    const int gq   = lane >> 2;   // groupID (0..7)
    const int t    = lane & 3;    // threadID-in-group
    const int gr   = blockIdx.x >> 3;
    const int i0   = (blockIdx.x & 7) << 7;

    // stage s2 for this graph (1024 floats, one float4 per thread)
    ((float4*)s2s)[tid] = ((const float4*)(g_s2 + (size_t)gr * NN))[tid];

    const int r0 = i0 + w * 16 + gq;
    const int r1 = r0 + 8;
    const float s1_0 = g_s1[(size_t)gr * NN + r0];
    const float s1_1 = g_s1[(size_t)gr * NN + r1];
    const int* arow0 = adj + ((size_t)gr * NN + r0) * NN;
    const int* arow1 = adj + ((size_t)gr * NN + r1) * NN;
    const float* Whg = g_Wh + (size_t)gr * NN * FF;

    float acc[8][4];
    #pragma unroll
    for (int nt = 0; nt < 8; nt++)
        #pragma unroll
        for (int q = 0; q < 4; q++) acc[nt][q] = 0.f;
    float Z0 = 0.f, Z1 = 0.f;

    // prefetch Wh chunk 0 into registers
    float4 v0 = ((const float4*)Whg)[tid];
    float4 v1 = ((const float4*)Whg)[tid + 256];

    for (int jc = 0; jc < 32; jc++) {
        __syncthreads();   // all warps done reading Whs from previous chunk
        {   // store prefetched chunk (tf32-rounded); float4 f -> k=f>>4, n4=f&15
            int k0 = tid >> 4, n0 = (tid & 15) * 4;
            Whs[k0 * BPITCH + n0 + 0] = f2tf32(v0.x);
            Whs[k0 * BPITCH + n0 + 1] = f2tf32(v0.y);
            Whs[k0 * BPITCH + n0 + 2] = f2tf32(v0.z);
            Whs[k0 * BPITCH + n0 + 3] = f2tf32(v0.w);
            int f1 = tid + 256, k1 = f1 >> 4, n1 = (f1 & 15) * 4;
            Whs[k1 * BPITCH + n1 + 0] = f2tf32(v1.x);
            Whs[k1 * BPITCH + n1 + 1] = f2tf32(v1.y);
            Whs[k1 * BPITCH + n1 + 2] = f2tf32(v1.z);
            Whs[k1 * BPITCH + n1 + 3] = f2tf32(v1.w);
        }
        if (jc + 1 < 32) {   // prefetch next chunk (latency hidden by compute)
            const float4* nxt = (const float4*)(Whg + (jc + 1) * 32 * FF);
            v0 = nxt[tid];
            v1 = nxt[tid + 256];
        }
        const int j0 = jc * 32;

        // prefetch the 16 adjacency values this thread needs for the chunk
        int am[4][4];
        #pragma unroll
        for (int ks = 0; ks < 4; ks++) {
            int kb = j0 + ks * 8 + t;
            am[ks][0] = arow0[kb];
            am[ks][1] = arow0[kb + 4];
            am[ks][2] = arow1[kb];
            am[ks][3] = arow1[kb + 4];
        }
        __syncthreads();   // Whs stores visible

        #pragma unroll
        for (int ks = 0; ks < 4; ks++) {
            const int kb = ks * 8 + t;
            const float s2a = s2s[j0 + kb];
            const float s2b = s2s[j0 + kb + 4];

            float x00 = s1_0 + s2a, x01 = s1_0 + s2b;
            float x10 = s1_1 + s2a, x11 = s1_1 + s2b;
            x00 = fmaxf(x00, 0.2f * x00); x01 = fmaxf(x01, 0.2f * x01);
            x10 = fmaxf(x10, 0.2f * x10); x11 = fmaxf(x11, 0.2f * x11);
            float p00 = am[ks][0] ? f2tf32(__expf(x00)) : 0.f;
            float p01 = am[ks][1] ? f2tf32(__expf(x01)) : 0.f;
            float p10 = am[ks][2] ? f2tf32(__expf(x10)) : 0.f;
            float p11 = am[ks][3] ? f2tf32(__expf(x11)) : 0.f;
            Z0 += p00 + p01;
            Z1 += p10 + p11;

            const uint32_t a0 = __float_as_uint(p00);   // (r0, k=t)
            const uint32_t a1 = __float_as_uint(p10);   // (r1, k=t)
            const uint32_t a2 = __float_as_uint(p01);   // (r0, k=t+4)
            const uint32_t a3 = __float_as_uint(p11);   // (r1, k=t+4)

            #pragma unroll
            for (int nt = 0; nt < 8; nt++) {
                const uint32_t b0 = __float_as_uint(Whs[kb * BPITCH + nt * 8 + gq]);
                const uint32_t b1 = __float_as_uint(Whs[(kb + 4) * BPITCH + nt * 8 + gq]);
                asm volatile(
                    "mma.sync.aligned.m16n8k8.row.col.f32.tf32.tf32.f32 "
                    "{%0,%1,%2,%3}, {%4,%5,%6,%7}, {%8,%9}, {%0,%1,%2,%3};"
                    : "+f"(acc[nt][0]), "+f"(acc[nt][1]),
                      "+f"(acc[nt][2]), "+f"(acc[nt][3])
                    : "r"(a0), "r"(a1), "r"(a2), "r"(a3), "r"(b0), "r"(b1));
            }
        }
    }

    // Z lives sliced across the 4 lanes of each quad (k%4 partitions)
    Z0 += __shfl_xor_sync(0xffffffffu, Z0, 1);
    Z0 += __shfl_xor_sync(0xffffffffu, Z0, 2);
    Z1 += __shfl_xor_sync(0xffffffffu, Z1, 1);
    Z1 += __shfl_xor_sync(0xffffffffu, Z1, 2);
    const float inv0 = 1.0f / Z0;
    const float inv1 = 1.0f / Z1;

    // epilogue: c0:(r0,2t) c1:(r0,2t+1) c2:(r1,2t) c3:(r1,2t+1) per n-tile
    float* o0 = out + ((size_t)gr * NN + r0) * FF + 2 * t;
    float* o1 = out + ((size_t)gr * NN + r1) * FF + 2 * t;
    #pragma unroll
    for (int nt = 0; nt < 8; nt++) {
        float e0 = acc[nt][0] * inv0;
        float e1 = acc[nt][1] * inv0;
        float e2 = acc[nt][2] * inv1;
        float e3 = acc[nt][3] * inv1;
        e0 = e0 > 0.f ? e0 : expm1f(e0);
        e1 = e1 > 0.f ? e1 : expm1f(e1);
        e2 = e2 > 0.f ? e2 : expm1f(e2);
        e3 = e3 > 0.f ? e3 : expm1f(e3);
        *(float2*)(o0 + nt * 8) = make_float2(e0, e1);
        *(float2*)(o1 + nt * 8) = make_float2(e2, e3);
    }
}

// ---------------------------------------------------------------------------
extern "C" void kernel_launch(void* const* d_in, const int* in_sizes, int n_in,
                              void* d_out, int out_size) {
    const float* h   = (const float*)d_in[0];
    const int*   adj = (const int*)d_in[1];
    const float* W   = (const float*)d_in[2];
    const float* a   = (const float*)d_in[3];
    float* out = (float*)d_out;

    wh_kernel<<<G * NN / 8, 256>>>(h, W, a);
    attn_mma<<<G * 8, 256>>>(adj, out);
}

// round 5
// speedup vs baseline: 2.0264x; 1.3927x over previous
#include <cuda_runtime.h>
#include <math.h>
#include <stdint.h>

#define G 64      // B*T graphs
#define NN 1024   // nodes per graph
#define FF 64     // features
#define BPITCH 72 // smem row pitch (floats) for Whs -> conflict-free LDS

// Scratch (device globals: allocation-free rule)
__device__ float g_Wh[G * NN * FF];   // 16 MB (tf32-rounded)
__device__ float g_s1[G * NN];
__device__ float g_s2[G * NN];

__device__ __forceinline__ float f2tf32(float x) {
    float r;
    asm("cvt.rna.tf32.f32 %0, %1;" : "=f"(r) : "f"(x));
    return r;
}
__device__ __forceinline__ uint32_t smem_u32(const void* p) {
    uint32_t a;
    asm("{ .reg .u64 t; cvta.to.shared.u64 t, %1; cvt.u32.u64 %0, t; }"
        : "=r"(a) : "l"(p));
    return a;
}
#define CP_ASYNC16(dst, src) \
    asm volatile("cp.async.cg.shared.global [%0], [%1], 16;" \
                 :: "r"(dst), "l"(src) : "memory")
#define CP_COMMIT() asm volatile("cp.async.commit_group;" ::: "memory")
#define CP_WAIT(n)  asm volatile("cp.async.wait_group %0;" :: "n"(n) : "memory")

// ---------------------------------------------------------------------------
// Kernel A: Wh = h @ W (stored tf32-rounded), s1 = Wh@a1, s2 = Wh@a2.
// ---------------------------------------------------------------------------
__global__ __launch_bounds__(256) void wh_kernel(const float* __restrict__ h,
                                                 const float* __restrict__ W,
                                                 const float* __restrict__ a) {
    __shared__ float2 Ws[64 * 32];
    int tid = threadIdx.x;
    {
        const float4* W4 = (const float4*)W;
        float4* Ws4 = (float4*)Ws;
        #pragma unroll
        for (int i = 0; i < 4; i++) Ws4[tid + i * 256] = W4[tid + i * 256];
    }
    __syncthreads();

    int lane = tid & 31;
    int warp = tid >> 5;
    int node = blockIdx.x * 8 + warp;

    float2 hv = ((const float2*)(h + (size_t)node * FF))[lane];

    float accx = 0.f, accy = 0.f;
    #pragma unroll
    for (int k = 0; k < 64; k++) {
        float hk = __shfl_sync(0xffffffffu, (k & 1) ? hv.y : hv.x, k >> 1);
        float2 w2 = Ws[k * 32 + lane];
        accx = fmaf(hk, w2.x, accx);
        accy = fmaf(hk, w2.y, accy);
    }
    // store tf32-rounded so the attention MMA's B-side truncation is a no-op
    ((float2*)(g_Wh + (size_t)node * FF))[lane] =
        make_float2(f2tf32(accx), f2tf32(accy));

    float2 a1 = __ldg(((const float2*)a) + lane);
    float2 a2 = __ldg(((const float2*)a) + 32 + lane);
    float s1 = accx * a1.x + accy * a1.y;
    float s2 = accx * a2.x + accy * a2.y;
    #pragma unroll
    for (int off = 16; off; off >>= 1) {
        s1 += __shfl_xor_sync(0xffffffffu, s1, off);
        s2 += __shfl_xor_sync(0xffffffffu, s2, off);
    }
    if (lane == 0) { g_s1[node] = s1; g_s2[node] = s2; }
}

// ---------------------------------------------------------------------------
// Kernel C: out[64,64] per CTA = softmax_mask(P) @ Wh via mma.sync m16n8k8.
// 4 warps, warp w owns rows [i0+16w, i0+16w+16). adj is ballot-compressed
// per chunk (1 coalesced LDG.32 per row). Wh chunks staged by cp.async
// (double-buffered). Grid 1024, launch_bounds(128,7) -> single wave.
// ---------------------------------------------------------------------------
__global__ __launch_bounds__(128, 7) void attn_mma(const int* __restrict__ adj,
                                                   float* __restrict__ out) {
    __shared__ float    s2s[NN];                 // 4 KB
    __shared__ float    Whs[2][32 * BPITCH];     // 18.4 KB, tf32 values
    __shared__ uint32_t masksS[4][16];           // per-warp row masks

    const int tid  = threadIdx.x;
    const int lane = tid & 31;
    const int w    = tid >> 5;
    const int gq   = lane >> 2;   // groupID (0..7)
    const int t    = lane & 3;    // threadID-in-group
    const int gr   = blockIdx.x >> 4;
    const int i0   = (blockIdx.x & 15) << 6;

    // stage s2 for this graph (1024 floats, two float4 per thread)
    {
        const float4* src = (const float4*)(g_s2 + (size_t)gr * NN);
        ((float4*)s2s)[tid]       = src[tid];
        ((float4*)s2s)[tid + 128] = src[tid + 128];
    }

    const float* Whg = g_Wh + (size_t)gr * NN * FF;
    const uint32_t whsb[2] = { smem_u32(&Whs[0][0]), smem_u32(&Whs[1][0]) };

    // cp.async chunk 0 -> buf 0
    {
        const int k = tid >> 4, seg = (tid & 15) * 4;
        #pragma unroll
        for (int q = 0; q < 4; q++) {
            int kk = k + q * 8;
            CP_ASYNC16(whsb[0] + (uint32_t)(kk * BPITCH + seg) * 4,
                       Whg + kk * FF + seg);
        }
        CP_COMMIT();
    }

    const int* abase = adj + ((size_t)gr * NN + i0 + w * 16) * NN;
    const int r0 = i0 + w * 16 + gq;
    const int r1 = r0 + 8;
    const float s1_0 = g_s1[(size_t)gr * NN + r0];
    const float s1_1 = g_s1[(size_t)gr * NN + r1];

    // adj prefetch for chunk 0: row r, element lane
    int av[16];
    #pragma unroll
    for (int r = 0; r < 16; r++) av[r] = abase[r * NN + lane];

    float acc[8][4];
    #pragma unroll
    for (int nt = 0; nt < 8; nt++)
        #pragma unroll
        for (int q = 0; q < 4; q++) acc[nt][q] = 0.f;
    float Z0 = 0.f, Z1 = 0.f;

    for (int jc = 0; jc < 32; jc++) {
        __syncthreads();   // all warps done computing chunk jc-1
        if (jc < 31) {     // stage chunk jc+1 into buf[(jc+1)&1]
            const float* srcn = Whg + (jc + 1) * 32 * FF;
            const uint32_t dstb = whsb[(jc + 1) & 1];
            const int k = tid >> 4, seg = (tid & 15) * 4;
            #pragma unroll
            for (int q = 0; q < 4; q++) {
                int kk = k + q * 8;
                CP_ASYNC16(dstb + (uint32_t)(kk * BPITCH + seg) * 4,
                           srcn + kk * FF + seg);
            }
            CP_COMMIT();
            CP_WAIT(1);    // chunk jc's group complete
        } else {
            CP_WAIT(0);
        }
        __syncthreads();   // chunk jc visible to all

        // ballot-compress this chunk's adjacency (16 rows x 32 j)
        __syncwarp();
        #pragma unroll
        for (int r = 0; r < 16; r++) {
            uint32_t m = __ballot_sync(0xffffffffu, av[r] != 0);
            if (lane == r) masksS[w][r] = m;
        }
        __syncwarp();
        const uint32_t mask0 = masksS[w][gq];
        const uint32_t mask1 = masksS[w][gq + 8];

        if (jc < 31) {     // prefetch adj for chunk jc+1
            const int joff = (jc + 1) * 32 + lane;
            #pragma unroll
            for (int r = 0; r < 16; r++) av[r] = abase[r * NN + joff];
        }

        const float* Wc = Whs[jc & 1];
        const int j0 = jc * 32;

        #pragma unroll
        for (int ks = 0; ks < 4; ks++) {
            const int kb = ks * 8 + t;
            const float s2a = s2s[j0 + kb];
            const float s2b = s2s[j0 + kb + 4];

            float x00 = s1_0 + s2a, x01 = s1_0 + s2b;
            float x10 = s1_1 + s2a, x11 = s1_1 + s2b;
            x00 = fmaxf(x00, 0.2f * x00); x01 = fmaxf(x01, 0.2f * x01);
            x10 = fmaxf(x10, 0.2f * x10); x11 = fmaxf(x11, 0.2f * x11);
            float p00 = ((mask0 >> kb) & 1u)       ? f2tf32(__expf(x00)) : 0.f;
            float p01 = ((mask0 >> (kb + 4)) & 1u) ? f2tf32(__expf(x01)) : 0.f;
            float p10 = ((mask1 >> kb) & 1u)       ? f2tf32(__expf(x10)) : 0.f;
            float p11 = ((mask1 >> (kb + 4)) & 1u) ? f2tf32(__expf(x11)) : 0.f;
            Z0 += p00 + p01;
            Z1 += p10 + p11;

            const uint32_t a0 = __float_as_uint(p00);
            const uint32_t a1 = __float_as_uint(p10);
            const uint32_t a2 = __float_as_uint(p01);
            const uint32_t a3 = __float_as_uint(p11);

            #pragma unroll
            for (int nt = 0; nt < 8; nt++) {
                const uint32_t b0 = __float_as_uint(Wc[kb * BPITCH + nt * 8 + gq]);
                const uint32_t b1 = __float_as_uint(Wc[(kb + 4) * BPITCH + nt * 8 + gq]);
                asm volatile(
                    "mma.sync.aligned.m16n8k8.row.col.f32.tf32.tf32.f32 "
                    "{%0,%1,%2,%3}, {%4,%5,%6,%7}, {%8,%9}, {%0,%1,%2,%3};"
                    : "+f"(acc[nt][0]), "+f"(acc[nt][1]),
                      "+f"(acc[nt][2]), "+f"(acc[nt][3])
                    : "r"(a0), "r"(a1), "r"(a2), "r"(a3), "r"(b0), "r"(b1));
            }
        }
    }

    // Z is sliced across the 4 lanes of each quad
    Z0 += __shfl_xor_sync(0xffffffffu, Z0, 1);
    Z0 += __shfl_xor_sync(0xffffffffu, Z0, 2);
    Z1 += __shfl_xor_sync(0xffffffffu, Z1, 1);
    Z1 += __shfl_xor_sync(0xffffffffu, Z1, 2);
    const float inv0 = 1.0f / Z0;
    const float inv1 = 1.0f / Z1;

    float* o0 = out + ((size_t)gr * NN + r0) * FF + 2 * t;
    float* o1 = out + ((size_t)gr * NN + r1) * FF + 2 * t;
    #pragma unroll
    for (int nt = 0; nt < 8; nt++) {
        float e0 = acc[nt][0] * inv0;
        float e1 = acc[nt][1] * inv0;
        float e2 = acc[nt][2] * inv1;
        float e3 = acc[nt][3] * inv1;
        e0 = e0 > 0.f ? e0 : expm1f(e0);
        e1 = e1 > 0.f ? e1 : expm1f(e1);
        e2 = e2 > 0.f ? e2 : expm1f(e2);
        e3 = e3 > 0.f ? e3 : expm1f(e3);
        *(float2*)(o0 + nt * 8) = make_float2(e0, e1);
        *(float2*)(o1 + nt * 8) = make_float2(e2, e3);
    }
}

// ---------------------------------------------------------------------------
extern "C" void kernel_launch(void* const* d_in, const int* in_sizes, int n_in,
                              void* d_out, int out_size) {
    const float* h   = (const float*)d_in[0];
    const int*   adj = (const int*)d_in[1];
    const float* W   = (const float*)d_in[2];
    const float* a   = (const float*)d_in[3];
    float* out = (float*)d_out;

    wh_kernel<<<G * NN / 8, 256>>>(h, W, a);
    attn_mma<<<G * 16, 128>>>(adj, out);
}

// round 7
// speedup vs baseline: 2.2633x; 1.1169x over previous
#include <cuda_runtime.h>
#include <math.h>
#include <stdint.h>

#define G 64      // B*T graphs
#define NN 1024   // nodes per graph
#define FF 64     // features
#define WP 72     // smem pitch (floats) for B tiles -> conflict-free LDS
#define MP 36     // mask smem pitch (words): 144B, 16B-aligned for cp.async

// Scratch (device globals: allocation-free rule)
__device__ float    g_Wh[G * NN * FF];      // 16 MB (tf32-rounded)
__device__ float    g_s1[G * NN];
__device__ float    g_s2[G * NN];
__device__ uint32_t g_mask[G * NN * 32];    // 8 MB adjacency bitmasks

__device__ __forceinline__ float f2tf32(float x) {
    float r;
    asm("cvt.rna.tf32.f32 %0, %1;" : "=f"(r) : "f"(x));
    return r;
}
__device__ __forceinline__ uint32_t smem_u32(const void* p) {
    uint32_t a;
    asm("{ .reg .u64 t; cvta.to.shared.u64 t, %1; cvt.u32.u64 %0, t; }"
        : "=r"(a) : "l"(p));
    return a;
}
#define CP_ASYNC16(dst, src) \
    asm volatile("cp.async.cg.shared.global [%0], [%1], 16;" \
                 :: "r"(dst), "l"(src) : "memory")
#define CP_COMMIT() asm volatile("cp.async.commit_group;" ::: "memory")
#define CP_WAIT(n)  asm volatile("cp.async.wait_group %0;" :: "n"(n) : "memory")

#define MMA_TF32(acc, a0, a1, a2, a3, b0, b1) \
    asm volatile( \
        "mma.sync.aligned.m16n8k8.row.col.f32.tf32.tf32.f32 " \
        "{%0,%1,%2,%3}, {%4,%5,%6,%7}, {%8,%9}, {%0,%1,%2,%3};" \
        : "+f"((acc)[0]), "+f"((acc)[1]), "+f"((acc)[2]), "+f"((acc)[3]) \
        : "r"(a0), "r"(a1), "r"(a2), "r"(a3), "r"(b0), "r"(b1))

// ---------------------------------------------------------------------------
// Kernel P (fused prep):
//  blocks [0,512):    Wh = h @ W via mma.sync; s1 = Wh@a1, s2 = Wh@a2.
//  blocks [512,1536): adj -> bitmask compression (DRAM-bound streaming).
// ---------------------------------------------------------------------------
__global__ __launch_bounds__(256) void prep_kernel(const float* __restrict__ h,
                                                   const int* __restrict__ adj,
                                                   const float* __restrict__ W,
                                                   const float* __restrict__ a) {
    __shared__ float Ws[64 * WP];   // 18.4 KB, W tf32-rounded, [k][f]
    __shared__ float sA[128];       // a vector

    const int tid  = threadIdx.x;
    const int lane = tid & 31;
    const int w    = tid >> 5;

    if (blockIdx.x >= 512) {
        // ---- compress: 8 warps x 8 rows = 64 rows per CTA ----
        const int rbase = (blockIdx.x - 512) * 64 + w * 8;
        #pragma unroll 1
        for (int r = 0; r < 8; r++) {
            const int row = rbase + r;
            const int* arow = adj + (size_t)row * NN;
            uint32_t mval = 0;
            #pragma unroll
            for (int wd = 0; wd < 32; wd++) {
                int v = arow[wd * 32 + lane];
                uint32_t m = __ballot_sync(0xffffffffu, v != 0);
                if (lane == wd) mval = m;
            }
            g_mask[(size_t)row * 32 + lane] = mval;
        }
        return;
    }

    // ---- wh via mma: CTA covers 128 rows ----
    #pragma unroll
    for (int i = 0; i < 16; i++) {
        int idx = tid + i * 256;              // 0..4095
        int k = idx >> 6, f = idx & 63;
        Ws[k * WP + f] = f2tf32(W[idx]);
    }
    if (tid < 128) sA[tid] = a[tid];
    __syncthreads();

    const int gq = lane >> 2;
    const int t  = lane & 3;
    const int r0 = blockIdx.x * 128 + w * 16 + gq;   // global node row
    const int r1 = r0 + 8;
    const float* h0 = h + (size_t)r0 * FF;
    const float* h1 = h + (size_t)r1 * FF;

    float acc[8][4];
    #pragma unroll
    for (int nt = 0; nt < 8; nt++)
        #pragma unroll
        for (int q = 0; q < 4; q++) acc[nt][q] = 0.f;

    #pragma unroll
    for (int ks = 0; ks < 8; ks++) {
        const int kb = ks * 8 + t;
        const uint32_t a0 = __float_as_uint(f2tf32(h0[kb]));
        const uint32_t a1 = __float_as_uint(f2tf32(h1[kb]));
        const uint32_t a2 = __float_as_uint(f2tf32(h0[kb + 4]));
        const uint32_t a3 = __float_as_uint(f2tf32(h1[kb + 4]));
        #pragma unroll
        for (int nt = 0; nt < 8; nt++) {
            const uint32_t b0 = __float_as_uint(Ws[kb * WP + nt * 8 + gq]);
            const uint32_t b1 = __float_as_uint(Ws[(kb + 4) * WP + nt * 8 + gq]);
            MMA_TF32(acc[nt], a0, a1, a2, a3, b0, b1);
        }
    }

    // store Wh (tf32-rounded) and accumulate s-dots
    float s1_0 = 0.f, s2_0 = 0.f, s1_1 = 0.f, s2_1 = 0.f;
    float* o0 = g_Wh + (size_t)r0 * FF + 2 * t;
    float* o1 = g_Wh + (size_t)r1 * FF + 2 * t;
    #pragma unroll
    for (int nt = 0; nt < 8; nt++) {
        const int c = nt * 8 + 2 * t;
        const float a1c0 = sA[c],      a1c1 = sA[c + 1];
        const float a2c0 = sA[64 + c], a2c1 = sA[64 + c + 1];
        s1_0 += acc[nt][0] * a1c0 + acc[nt][1] * a1c1;
        s2_0 += acc[nt][0] * a2c0 + acc[nt][1] * a2c1;
        s1_1 += acc[nt][2] * a1c0 + acc[nt][3] * a1c1;
        s2_1 += acc[nt][2] * a2c0 + acc[nt][3] * a2c1;
        *(float2*)(o0 + nt * 8) = make_float2(f2tf32(acc[nt][0]), f2tf32(acc[nt][1]));
        *(float2*)(o1 + nt * 8) = make_float2(f2tf32(acc[nt][2]), f2tf32(acc[nt][3]));
    }
    #pragma unroll
    for (int off = 1; off <= 2; off <<= 1) {
        s1_0 += __shfl_xor_sync(0xffffffffu, s1_0, off);
        s2_0 += __shfl_xor_sync(0xffffffffu, s2_0, off);
        s1_1 += __shfl_xor_sync(0xffffffffu, s1_1, off);
        s2_1 += __shfl_xor_sync(0xffffffffu, s2_1, off);
    }
    if (t == 0) {
        g_s1[r0] = s1_0; g_s2[r0] = s2_0;
        g_s1[r1] = s1_1; g_s2[r1] = s2_1;
    }
}

// ---------------------------------------------------------------------------
// Kernel C: out[128,64] per CTA = softmax_mask(P) @ Wh, mma.sync m16n8k8 tf32.
// Masks smem-resident (staged once); P from factorized exp tables (no MUFU,
// no LDG in the hot loop). Wh chunks double-buffered via cp.async.
// ---------------------------------------------------------------------------
// dynamic smem (bytes):
//  tab    float4[1024]  @ 0       (16384)  {s2, e^{s2}, e^{0.2 s2}, 0}
//  maskS  u32[128*MP]   @ 16384   (18432)  pitch 36 words (144B, 16B-aligned)
//  Whs0   f32[32*WP]    @ 34816   (9216)
//  Whs1   f32[32*WP]    @ 44032   (9216)   total 53248
#define OFF_TAB  0
#define OFF_MASK 16384
#define OFF_WHS0 34816
#define OFF_WHS1 44032
#define ATTN_SMEM 53248

extern __shared__ char smc[];

__global__ __launch_bounds__(256, 4) void attn_mma(float* __restrict__ out) {
    float4*   tab   = (float4*)(smc + OFF_TAB);
    uint32_t* maskS = (uint32_t*)(smc + OFF_MASK);
    const uint32_t sb = smem_u32(smc);

    const int tid  = threadIdx.x;
    const int lane = tid & 31;
    const int w    = tid >> 5;
    const int gq   = lane >> 2;
    const int t    = lane & 3;
    const int gr   = blockIdx.x >> 3;
    const int i0   = (blockIdx.x & 7) << 7;

    const float* Whg = g_Wh + (size_t)gr * NN * FF;

    // stage masks (pitch MP=36) + Wh chunk 0; build exp table
    {
        const uint32_t* msrc = g_mask + ((size_t)gr * NN + i0) * 32;
        #pragma unroll
        for (int q = 0; q < 4; q++) {
            int idx = tid * 4 + q;            // 0..1023 (row-quad units)
            int r = idx >> 3, s4 = (idx & 7) * 4;
            CP_ASYNC16(sb + OFF_MASK + (uint32_t)(r * MP + s4) * 4,
                       msrc + r * 32 + s4);
        }
        #pragma unroll
        for (int q = 0; q < 2; q++) {
            int idx = tid + q * 256;          // 0..511
            int k = idx >> 4, s4 = (idx & 15) * 4;
            CP_ASYNC16(sb + OFF_WHS0 + (uint32_t)(k * WP + s4) * 4,
                       Whg + k * FF + s4);
        }
        CP_COMMIT();
        const float4 s2v = ((const float4*)(g_s2 + (size_t)gr * NN))[tid];
        tab[tid * 4 + 0] = make_float4(s2v.x, __expf(s2v.x), __expf(0.2f * s2v.x), 0.f);
        tab[tid * 4 + 1] = make_float4(s2v.y, __expf(s2v.y), __expf(0.2f * s2v.y), 0.f);
        tab[tid * 4 + 2] = make_float4(s2v.z, __expf(s2v.z), __expf(0.2f * s2v.z), 0.f);
        tab[tid * 4 + 3] = make_float4(s2v.w, __expf(s2v.w), __expf(0.2f * s2v.w), 0.f);
    }

    const int lr0 = w * 16 + gq;                 // CTA-local row
    const int lr1 = lr0 + 8;
    const float s1_0 = g_s1[(size_t)gr * NN + i0 + lr0];
    const float s1_1 = g_s1[(size_t)gr * NN + i0 + lr1];
    const float e1_0 = __expf(s1_0), e1b_0 = __expf(0.2f * s1_0), thr0 = -s1_0;
    const float e1_1 = __expf(s1_1), e1b_1 = __expf(0.2f * s1_1), thr1 = -s1_1;

    float acc[8][4];
    #pragma unroll
    for (int nt = 0; nt < 8; nt++)
        #pragma unroll
        for (int q = 0; q < 4; q++) acc[nt][q] = 0.f;
    float Z0 = 0.f, Z1 = 0.f;

    CP_WAIT(0);
    __syncthreads();

    const uint32_t whoff[2] = { OFF_WHS0, OFF_WHS1 };

    for (int jc = 0; jc < 32; jc++) {
        if (jc > 0) __syncthreads();   // all warps done reading buf (jc+1)&1
        if (jc < 31) {                 // stage chunk jc+1
            const float* srcn = Whg + (jc + 1) * 32 * FF;
            const uint32_t dstb = sb + whoff[(jc + 1) & 1];
            #pragma unroll
            for (int q = 0; q < 2; q++) {
                int idx = tid + q * 256;
                int k = idx >> 4, s4 = (idx & 15) * 4;
                CP_ASYNC16(dstb + (uint32_t)(k * WP + s4) * 4,
                           srcn + k * FF + s4);
            }
            CP_COMMIT();
            CP_WAIT(1);
        } else {
            CP_WAIT(0);
        }
        __syncthreads();

        const float* Wc = (const float*)(smc + whoff[jc & 1]);
        const uint32_t m0 = maskS[lr0 * MP + jc];
        const uint32_t m1 = maskS[lr1 * MP + jc];
        const int j0 = jc * 32;

        #pragma unroll
        for (int ks = 0; ks < 4; ks++) {
            const int kb = ks * 8 + t;
            const float4 ta = tab[j0 + kb];
            const float4 tb = tab[j0 + kb + 4];

            const bool c00 = ta.x > thr0, c01 = tb.x > thr0;
            const bool c10 = ta.x > thr1, c11 = tb.x > thr1;
            float p00 = (c00 ? e1_0 : e1b_0) * (c00 ? ta.y : ta.z);
            float p01 = (c01 ? e1_0 : e1b_0) * (c01 ? tb.y : tb.z);
            float p10 = (c10 ? e1_1 : e1b_1) * (c10 ? ta.y : ta.z);
            float p11 = (c11 ? e1_1 : e1b_1) * (c11 ? tb.y : tb.z);
            p00 = ((m0 >> kb) & 1u)       ? f2tf32(p00) : 0.f;
            p01 = ((m0 >> (kb + 4)) & 1u) ? f2tf32(p01) : 0.f;
            p10 = ((m1 >> kb) & 1u)       ? f2tf32(p10) : 0.f;
            p11 = ((m1 >> (kb + 4)) & 1u) ? f2tf32(p11) : 0.f;
            Z0 += p00 + p01;
            Z1 += p10 + p11;

            const uint32_t a0 = __float_as_uint(p00);
            const uint32_t a1 = __float_as_uint(p10);
            const uint32_t a2 = __float_as_uint(p01);
            const uint32_t a3 = __float_as_uint(p11);

            #pragma unroll
            for (int nt = 0; nt < 8; nt++) {
                const uint32_t b0 = __float_as_uint(Wc[kb * WP + nt * 8 + gq]);
                const uint32_t b1 = __float_as_uint(Wc[(kb + 4) * WP + nt * 8 + gq]);
                MMA_TF32(acc[nt], a0, a1, a2, a3, b0, b1);
            }
        }
    }

    // Z sliced across quad lanes
    #pragma unroll
    for (int off = 1; off <= 2; off <<= 1) {
        Z0 += __shfl_xor_sync(0xffffffffu, Z0, off);
        Z1 += __shfl_xor_sync(0xffffffffu, Z1, off);
    }
    const float inv0 = 1.0f / Z0;
    const float inv1 = 1.0f / Z1;

    float* o0 = out + ((size_t)gr * NN + i0 + lr0) * FF + 2 * t;
    float* o1 = out + ((size_t)gr * NN + i0 + lr1) * FF + 2 * t;
    #pragma unroll
    for (int nt = 0; nt < 8; nt++) {
        float e0 = acc[nt][0] * inv0;
        float e1 = acc[nt][1] * inv0;
        float e2 = acc[nt][2] * inv1;
        float e3 = acc[nt][3] * inv1;
        e0 = e0 > 0.f ? e0 : expm1f(e0);
        e1 = e1 > 0.f ? e1 : expm1f(e1);
        e2 = e2 > 0.f ? e2 : expm1f(e2);
        e3 = e3 > 0.f ? e3 : expm1f(e3);
        *(float2*)(o0 + nt * 8) = make_float2(e0, e1);
        *(float2*)(o1 + nt * 8) = make_float2(e2, e3);
    }
}

// ---------------------------------------------------------------------------
extern "C" void kernel_launch(void* const* d_in, const int* in_sizes, int n_in,
                              void* d_out, int out_size) {
    const float* h   = (const float*)d_in[0];
    const int*   adj = (const int*)d_in[1];
    const float* W   = (const float*)d_in[2];
    const float* a   = (const float*)d_in[3];
    float* out = (float*)d_out;

    cudaFuncSetAttribute(attn_mma, cudaFuncAttributeMaxDynamicSharedMemorySize,
                         ATTN_SMEM);

    prep_kernel<<<512 + 1024, 256>>>(h, adj, W, a);
    attn_mma<<<G * 8, 256, ATTN_SMEM>>>(out);
}

// round 8
// speedup vs baseline: 2.5134x; 1.1105x over previous
#include <cuda_runtime.h>
#include <math.h>
#include <stdint.h>

#define G 64      // B*T graphs
#define NN 1024   // nodes per graph
#define FF 64     // features
#define WP 72     // smem pitch (floats) for B tiles -> conflict-free LDS
#define MP 36     // mask smem pitch (words): 144B, 16B-aligned for cp.async

// Scratch (device globals: allocation-free rule)
__device__ float    g_Wh[G * NN * FF];      // 16 MB (tf32-rounded)
__device__ float    g_s1[G * NN];
__device__ float    g_s2[G * NN];
__device__ uint32_t g_mask[G * NN * 32];    // 8 MB adjacency bitmasks (permuted)

__device__ __forceinline__ float f2tf32(float x) {
    float r;
    asm("cvt.rna.tf32.f32 %0, %1;" : "=f"(r) : "f"(x));
    return r;
}
__device__ __forceinline__ uint32_t smem_u32(const void* p) {
    uint32_t a;
    asm("{ .reg .u64 t; cvta.to.shared.u64 t, %1; cvt.u32.u64 %0, t; }"
        : "=r"(a) : "l"(p));
    return a;
}
#define CP_ASYNC16(dst, src) \
    asm volatile("cp.async.cg.shared.global [%0], [%1], 16;" \
                 :: "r"(dst), "l"(src) : "memory")
#define CP_COMMIT() asm volatile("cp.async.commit_group;" ::: "memory")
#define CP_WAIT(n)  asm volatile("cp.async.wait_group %0;" :: "n"(n) : "memory")

#define MMA_TF32(acc, a0, a1, a2, a3, b0, b1) \
    asm volatile( \
        "mma.sync.aligned.m16n8k8.row.col.f32.tf32.tf32.f32 " \
        "{%0,%1,%2,%3}, {%4,%5,%6,%7}, {%8,%9}, {%0,%1,%2,%3};" \
        : "+f"((acc)[0]), "+f"((acc)[1]), "+f"((acc)[2]), "+f"((acc)[3]) \
        : "r"(a0), "r"(a1), "r"(a2), "r"(a3), "r"(b0), "r"(b1))

// ---------------------------------------------------------------------------
// Kernel P (fused prep):
//  blocks [0,512):    Wh = h @ W via mma.sync; s1 = Wh@a1, s2 = Wh@a2.
//  blocks [512,1536): adj -> permuted bitmask compression (int4 + ballot).
//  mask word (p,c) bit l = adj[row][p*128 + 4l + c];  stored at row*32+p*4+c.
// ---------------------------------------------------------------------------
__global__ __launch_bounds__(256) void prep_kernel(const float* __restrict__ h,
                                                   const int* __restrict__ adj,
                                                   const float* __restrict__ W,
                                                   const float* __restrict__ a) {
    __shared__ float Ws[64 * WP];   // 18.4 KB, W tf32-rounded, [k][f]
    __shared__ float sA[128];       // a vector

    const int tid  = threadIdx.x;
    const int lane = tid & 31;
    const int w    = tid >> 5;

    if (blockIdx.x >= 512) {
        // ---- compress: 8 warps x 8 rows = 64 rows per CTA ----
        const int rbase = (blockIdx.x - 512) * 64 + w * 8;
        #pragma unroll 1
        for (int r = 0; r < 8; r++) {
            const int row = rbase + r;
            const int4* arow4 = (const int4*)(adj + (size_t)row * NN);
            uint32_t mval = 0;
            #pragma unroll
            for (int p = 0; p < 8; p++) {
                int4 v = arow4[p * 32 + lane];
                uint32_t b0 = __ballot_sync(0xffffffffu, v.x != 0);
                uint32_t b1 = __ballot_sync(0xffffffffu, v.y != 0);
                uint32_t b2 = __ballot_sync(0xffffffffu, v.z != 0);
                uint32_t b3 = __ballot_sync(0xffffffffu, v.w != 0);
                if (lane == p * 4 + 0) mval = b0;
                if (lane == p * 4 + 1) mval = b1;
                if (lane == p * 4 + 2) mval = b2;
                if (lane == p * 4 + 3) mval = b3;
            }
            g_mask[(size_t)row * 32 + lane] = mval;
        }
        return;
    }

    // ---- wh via mma: CTA covers 128 rows ----
    #pragma unroll
    for (int i = 0; i < 16; i++) {
        int idx = tid + i * 256;              // 0..4095
        int k = idx >> 6, f = idx & 63;
        Ws[k * WP + f] = f2tf32(W[idx]);
    }
    if (tid < 128) sA[tid] = a[tid];
    __syncthreads();

    const int gq = lane >> 2;
    const int t  = lane & 3;
    const int r0 = blockIdx.x * 128 + w * 16 + gq;   // global node row
    const int r1 = r0 + 8;
    const float* h0 = h + (size_t)r0 * FF;
    const float* h1 = h + (size_t)r1 * FF;

    float acc[8][4];
    #pragma unroll
    for (int nt = 0; nt < 8; nt++)
        #pragma unroll
        for (int q = 0; q < 4; q++) acc[nt][q] = 0.f;

    #pragma unroll
    for (int ks = 0; ks < 8; ks++) {
        const int kb = ks * 8 + t;
        const uint32_t a0 = __float_as_uint(f2tf32(h0[kb]));
        const uint32_t a1 = __float_as_uint(f2tf32(h1[kb]));
        const uint32_t a2 = __float_as_uint(f2tf32(h0[kb + 4]));
        const uint32_t a3 = __float_as_uint(f2tf32(h1[kb + 4]));
        #pragma unroll
        for (int nt = 0; nt < 8; nt++) {
            const uint32_t b0 = __float_as_uint(Ws[kb * WP + nt * 8 + gq]);
            const uint32_t b1 = __float_as_uint(Ws[(kb + 4) * WP + nt * 8 + gq]);
            MMA_TF32(acc[nt], a0, a1, a2, a3, b0, b1);
        }
    }

    // store Wh (tf32-rounded) and accumulate s-dots
    float s1_0 = 0.f, s2_0 = 0.f, s1_1 = 0.f, s2_1 = 0.f;
    float* o0 = g_Wh + (size_t)r0 * FF + 2 * t;
    float* o1 = g_Wh + (size_t)r1 * FF + 2 * t;
    #pragma unroll
    for (int nt = 0; nt < 8; nt++) {
        const int c = nt * 8 + 2 * t;
        const float a1c0 = sA[c],      a1c1 = sA[c + 1];
        const float a2c0 = sA[64 + c], a2c1 = sA[64 + c + 1];
        s1_0 += acc[nt][0] * a1c0 + acc[nt][1] * a1c1;
        s2_0 += acc[nt][0] * a2c0 + acc[nt][1] * a2c1;
        s1_1 += acc[nt][2] * a1c0 + acc[nt][3] * a1c1;
        s2_1 += acc[nt][2] * a2c0 + acc[nt][3] * a2c1;
        *(float2*)(o0 + nt * 8) = make_float2(f2tf32(acc[nt][0]), f2tf32(acc[nt][1]));
        *(float2*)(o1 + nt * 8) = make_float2(f2tf32(acc[nt][2]), f2tf32(acc[nt][3]));
    }
    #pragma unroll
    for (int off = 1; off <= 2; off <<= 1) {
        s1_0 += __shfl_xor_sync(0xffffffffu, s1_0, off);
        s2_0 += __shfl_xor_sync(0xffffffffu, s2_0, off);
        s1_1 += __shfl_xor_sync(0xffffffffu, s1_1, off);
        s2_1 += __shfl_xor_sync(0xffffffffu, s2_1, off);
    }
    if (t == 0) {
        g_s1[r0] = s1_0; g_s2[r0] = s2_0;
        g_s1[r1] = s1_1; g_s2[r1] = s2_1;
    }
}

// ---------------------------------------------------------------------------
// Kernel C: out[128,64] per CTA = softmax_mask(P) @ Wh, mma.sync m16n8k8 tf32.
// Z computed by the MMA itself (ones-column n-tile, constant B fragments).
// Masks smem-resident (permuted layout); factorized exp tables; cp.async
// double-buffered Wh tiles. No cvt / no Z adds / no LDG in the hot loop.
// ---------------------------------------------------------------------------
// dynamic smem (bytes):
//  tab    float4[1024]  @ 0       (16384)  {s2, e^{s2}, e^{0.2 s2}, 0}
//  maskS  u32[128*MP]   @ 16384   (18432)  pitch 36 words
//  Whs0   f32[32*WP]    @ 34816   (9216)
//  Whs1   f32[32*WP]    @ 44032   (9216)   total 53248
#define OFF_TAB  0
#define OFF_MASK 16384
#define OFF_WHS0 34816
#define OFF_WHS1 44032
#define ATTN_SMEM 53248

extern __shared__ char smc[];

__global__ __launch_bounds__(256, 4) void attn_mma(float* __restrict__ out) {
    float4*   tab   = (float4*)(smc + OFF_TAB);
    uint32_t* maskS = (uint32_t*)(smc + OFF_MASK);
    const uint32_t sb = smem_u32(smc);

    const int tid  = threadIdx.x;
    const int lane = tid & 31;
    const int w    = tid >> 5;
    const int gq   = lane >> 2;
    const int t    = lane & 3;
    const int gr   = blockIdx.x >> 3;
    const int i0   = (blockIdx.x & 7) << 7;

    const float* Whg = g_Wh + (size_t)gr * NN * FF;

    // stage masks (pitch MP) + Wh chunk 0; build exp table
    {
        const uint32_t* msrc = g_mask + ((size_t)gr * NN + i0) * 32;
        #pragma unroll
        for (int q = 0; q < 4; q++) {
            int idx = tid * 4 + q;            // 0..1023
            int r = idx >> 3, s4 = (idx & 7) * 4;
            CP_ASYNC16(sb + OFF_MASK + (uint32_t)(r * MP + s4) * 4,
                       msrc + r * 32 + s4);
        }
        #pragma unroll
        for (int q = 0; q < 2; q++) {
            int idx = tid + q * 256;          // 0..511
            int k = idx >> 4, s4 = (idx & 15) * 4;
            CP_ASYNC16(sb + OFF_WHS0 + (uint32_t)(k * WP + s4) * 4,
                       Whg + k * FF + s4);
        }
        CP_COMMIT();
        const float4 s2v = ((const float4*)(g_s2 + (size_t)gr * NN))[tid];
        tab[tid * 4 + 0] = make_float4(s2v.x, __expf(s2v.x), __expf(0.2f * s2v.x), 0.f);
        tab[tid * 4 + 1] = make_float4(s2v.y, __expf(s2v.y), __expf(0.2f * s2v.y), 0.f);
        tab[tid * 4 + 2] = make_float4(s2v.z, __expf(s2v.z), __expf(0.2f * s2v.z), 0.f);
        tab[tid * 4 + 3] = make_float4(s2v.w, __expf(s2v.w), __expf(0.2f * s2v.w), 0.f);
    }

    const int lr0 = w * 16 + gq;                 // CTA-local row
    const int lr1 = lr0 + 8;
    const float s1_0 = g_s1[(size_t)gr * NN + i0 + lr0];
    const float s1_1 = g_s1[(size_t)gr * NN + i0 + lr1];
    const float e1_0 = __expf(s1_0), e1b_0 = __expf(0.2f * s1_0), thr0 = -s1_0;
    const float e1_1 = __expf(s1_1), e1b_1 = __expf(0.2f * s1_1), thr1 = -s1_1;

    // acc[0..7]: Wh n-tiles; acc[8]: ones-column (Z) tile
    float acc[9][4];
    #pragma unroll
    for (int nt = 0; nt < 9; nt++)
        #pragma unroll
        for (int q = 0; q < 4; q++) acc[nt][q] = 0.f;

    // constant B fragment for the ones column: B[n'=gq][k] = (gq==0) ? 1 : 0
    const uint32_t bz = (gq == 0) ? 0x3f800000u : 0u;

    CP_WAIT(0);
    __syncthreads();

    const uint32_t whoff[2] = { OFF_WHS0, OFF_WHS1 };

    for (int jc = 0; jc < 32; jc++) {
        if (jc > 0) __syncthreads();   // all warps done reading buf (jc+1)&1
        if (jc < 31) {                 // stage chunk jc+1
            const float* srcn = Whg + (jc + 1) * 32 * FF;
            const uint32_t dstb = sb + whoff[(jc + 1) & 1];
            #pragma unroll
            for (int q = 0; q < 2; q++) {
                int idx = tid + q * 256;
                int k = idx >> 4, s4 = (idx & 15) * 4;
                CP_ASYNC16(dstb + (uint32_t)(k * WP + s4) * 4,
                           srcn + k * FF + s4);
            }
            CP_COMMIT();
            CP_WAIT(1);
        } else {
            CP_WAIT(0);
        }
        __syncthreads();

        const float* Wc = (const float*)(smc + whoff[jc & 1]);
        // permuted mask: word (jc>>2)*4 + t, byte (jc&3); bits 2ks / 2ks+1
        const int msh = (jc & 3) * 8;
        const uint32_t ms0 = maskS[lr0 * MP + (jc >> 2) * 4 + t] >> msh;
        const uint32_t ms1 = maskS[lr1 * MP + (jc >> 2) * 4 + t] >> msh;
        const int j0 = jc * 32;

        #pragma unroll
        for (int ks = 0; ks < 4; ks++) {
            const int kb = ks * 8 + t;
            const float4 ta = tab[j0 + kb];
            const float4 tb = tab[j0 + kb + 4];

            const bool c00 = ta.x > thr0, c01 = tb.x > thr0;
            const bool c10 = ta.x > thr1, c11 = tb.x > thr1;
            float p00 = c00 ? e1_0 * ta.y : e1b_0 * ta.z;
            float p01 = c01 ? e1_0 * tb.y : e1b_0 * tb.z;
            float p10 = c10 ? e1_1 * ta.y : e1b_1 * ta.z;
            float p11 = c11 ? e1_1 * tb.y : e1b_1 * tb.z;
            p00 = (ms0 & (1u << (2 * ks)))       ? p00 : 0.f;
            p01 = (ms0 & (2u << (2 * ks)))       ? p01 : 0.f;
            p10 = (ms1 & (1u << (2 * ks)))       ? p10 : 0.f;
            p11 = (ms1 & (2u << (2 * ks)))       ? p11 : 0.f;

            const uint32_t a0 = __float_as_uint(p00);
            const uint32_t a1 = __float_as_uint(p10);
            const uint32_t a2 = __float_as_uint(p01);
            const uint32_t a3 = __float_as_uint(p11);

            #pragma unroll
            for (int nt = 0; nt < 8; nt++) {
                const uint32_t b0 = __float_as_uint(Wc[kb * WP + nt * 8 + gq]);
                const uint32_t b1 = __float_as_uint(Wc[(kb + 4) * WP + nt * 8 + gq]);
                MMA_TF32(acc[nt], a0, a1, a2, a3, b0, b1);
            }
            MMA_TF32(acc[8], a0, a1, a2, a3, bz, bz);   // Z tile
        }
    }

    // Z = col 64 of the ones tile, held by t==0 lanes; broadcast to quad
    const float Z0 = __shfl_sync(0xffffffffu, acc[8][0], lane & 28);
    const float Z1 = __shfl_sync(0xffffffffu, acc[8][2], lane & 28);
    const float inv0 = 1.0f / Z0;
    const float inv1 = 1.0f / Z1;

    float* o0 = out + ((size_t)gr * NN + i0 + lr0) * FF + 2 * t;
    float* o1 = out + ((size_t)gr * NN + i0 + lr1) * FF + 2 * t;
    #pragma unroll
    for (int nt = 0; nt < 8; nt++) {
        float e0 = acc[nt][0] * inv0;
        float e1 = acc[nt][1] * inv0;
        float e2 = acc[nt][2] * inv1;
        float e3 = acc[nt][3] * inv1;
        e0 = e0 > 0.f ? e0 : expm1f(e0);
        e1 = e1 > 0.f ? e1 : expm1f(e1);
        e2 = e2 > 0.f ? e2 : expm1f(e2);
        e3 = e3 > 0.f ? e3 : expm1f(e3);
        *(float2*)(o0 + nt * 8) = make_float2(e0, e1);
        *(float2*)(o1 + nt * 8) = make_float2(e2, e3);
    }
}

// ---------------------------------------------------------------------------
extern "C" void kernel_launch(void* const* d_in, const int* in_sizes, int n_in,
                              void* d_out, int out_size) {
    const float* h   = (const float*)d_in[0];
    const int*   adj = (const int*)d_in[1];
    const float* W   = (const float*)d_in[2];
    const float* a   = (const float*)d_in[3];
    float* out = (float*)d_out;

    cudaFuncSetAttribute(attn_mma, cudaFuncAttributeMaxDynamicSharedMemorySize,
                         ATTN_SMEM);

    prep_kernel<<<512 + 1024, 256>>>(h, adj, W, a);
    attn_mma<<<G * 8, 256, ATTN_SMEM>>>(out);
}